// round 2
// baseline (speedup 1.0000x reference)
#include <cuda_runtime.h>
#include <cstdint>

#define NN  50000
#define EMBD 128
#define NE  500000

// scratch (allocation-free rule: __device__ globals)
__device__ __align__(16) float g_H1[NN * EMBD];
__device__ __align__(16) float g_acc[NN * EMBD];

// ---------------------------------------------------------------------------
// threefry2x32, JAX *partitionable* mode (jax_threefry_partitionable=True,
// the default in modern JAX): for flat element index i (< 2^32), counter is
// the 64-bit value i -> words (x0 = hi32 = 0, x1 = lo32 = i); key = (0, 42)
// from jax.random.key(42). 32-bit output = out0 ^ out1.
// ---------------------------------------------------------------------------
__device__ __forceinline__ unsigned tf_rotl(unsigned x, int r) {
    return __funnelshift_l(x, x, r);
}

__device__ __forceinline__ unsigned threefry_bits(unsigned flat) {
    unsigned x0 = 0u;      // high word of 64-bit counter (indices < 2^32)
    unsigned x1 = flat;    // low word
    const unsigned ks0 = 0u, ks1 = 42u, ks2 = 0x1BD11BDAu ^ 0u ^ 42u;
    x0 += ks0; x1 += ks1;
#define TF_R(r) { x0 += x1; x1 = tf_rotl(x1, r); x1 ^= x0; }
    TF_R(13) TF_R(15) TF_R(26) TF_R(6)
    x0 += ks1; x1 += ks2 + 1u;
    TF_R(17) TF_R(29) TF_R(16) TF_R(24)
    x0 += ks2; x1 += ks0 + 2u;
    TF_R(13) TF_R(15) TF_R(26) TF_R(6)
    x0 += ks0; x1 += ks1 + 3u;
    TF_R(17) TF_R(29) TF_R(16) TF_R(24)
    x0 += ks1; x1 += ks2 + 4u;
    TF_R(13) TF_R(15) TF_R(26) TF_R(6)
    x0 += ks2; x1 += ks0 + 5u;
#undef TF_R
    return x0 ^ x1;
}

// ---------------------------------------------------------------------------
// k1: H1[N,128] = hidden[N,128] @ W_msg[0:128,:] + b_msg
// block: 256 thr, tile 64 rows x 128 cols, thread = 8 rows x 4 cols
// ---------------------------------------------------------------------------
__global__ __launch_bounds__(256) void k1_node_gemm(
    const float* __restrict__ A, const float* __restrict__ W,
    const float* __restrict__ bias, float* __restrict__ out)
{
    extern __shared__ float sm[];
    float* Ws = sm;               // 128x128
    float* As = sm + 128 * 128;   // 64x128
    const int tid = threadIdx.x, tx = tid & 31, ty = tid >> 5;
    const int row0 = blockIdx.x * 64;

    float4* Ws4 = (float4*)Ws;
    const float4* Wg = (const float4*)W;
#pragma unroll
    for (int t = 0; t < 16; ++t) Ws4[tid + t * 256] = Wg[tid + t * 256];

    float4* As4 = (float4*)As;
    const float4* Ag = (const float4*)A;
#pragma unroll
    for (int t = 0; t < 8; ++t) {
        int idx = tid + t * 256;            // 0..2047: row=idx>>5, q=idx&31
        int r = row0 + (idx >> 5);
        As4[idx] = (r < NN) ? Ag[(size_t)r * 32 + (idx & 31)]
                            : make_float4(0.f, 0.f, 0.f, 0.f);
    }
    __syncthreads();

    float acc[8][4];
#pragma unroll
    for (int i = 0; i < 8; ++i) { acc[i][0] = acc[i][1] = acc[i][2] = acc[i][3] = 0.f; }

    const float4* Ar = (const float4*)(As + (ty * 8) * 128);
#pragma unroll 4
    for (int k4 = 0; k4 < 32; ++k4) {
        float4 a[8];
#pragma unroll
        for (int i = 0; i < 8; ++i) a[i] = Ar[i * 32 + k4];
#pragma unroll
        for (int kk = 0; kk < 4; ++kk) {
            const float* Bk = Ws + (k4 * 4 + kk) * 128 + tx;
            float b0 = Bk[0], b1 = Bk[32], b2 = Bk[64], b3 = Bk[96];
#pragma unroll
            for (int i = 0; i < 8; ++i) {
                float av = (kk == 0) ? a[i].x : (kk == 1) ? a[i].y : (kk == 2) ? a[i].z : a[i].w;
                acc[i][0] = fmaf(av, b0, acc[i][0]);
                acc[i][1] = fmaf(av, b1, acc[i][1]);
                acc[i][2] = fmaf(av, b2, acc[i][2]);
                acc[i][3] = fmaf(av, b3, acc[i][3]);
            }
        }
    }
    float bb0 = bias[tx], bb1 = bias[tx + 32], bb2 = bias[tx + 64], bb3 = bias[tx + 96];
#pragma unroll
    for (int i = 0; i < 8; ++i) {
        int r = row0 + ty * 8 + i;
        if (r < NN) {
            float* o = out + (size_t)r * 128;
            o[tx]      = acc[i][0] + bb0;
            o[tx + 32] = acc[i][1] + bb1;
            o[tx + 64] = acc[i][2] + bb2;
            o[tx + 96] = acc[i][3] + bb3;
        }
    }
}

// ---------------------------------------------------------------------------
// k2: per-edge  msg = relu(H1[src] + [ea|et] @ W_msg[128:192,:]) ;
//     atomicAdd into acc[dst].  GEMM tile: 64 edges x 128, K=64.
// ---------------------------------------------------------------------------
__global__ __launch_bounds__(256) void k2_edge(
    const float* __restrict__ eattr, const float* __restrict__ etime,
    const int* __restrict__ eidx, const float* __restrict__ W_msg,
    const float* __restrict__ H1, float* __restrict__ accum)
{
    extern __shared__ float sm[];
    float* Bs = sm;               // 64x128 (W23)
    float* As = sm + 64 * 128;    // 64x64  ([ea|et] tile)
    int* s_src = (int*)(sm + 64 * 128 + 64 * 64);
    int* s_dst = s_src + 64;
    const int tid = threadIdx.x, tx = tid & 31, ty = tid >> 5;
    const int e0 = blockIdx.x * 64;

    const float4* Wg = (const float4*)(W_msg + 128 * 128);
    float4* Bs4 = (float4*)Bs;
#pragma unroll
    for (int t = 0; t < 8; ++t) Bs4[tid + t * 256] = Wg[tid + t * 256];

    float4* As4 = (float4*)As;
    const float4* ag = (const float4*)eattr;
    const float4* tg = (const float4*)etime;
#pragma unroll
    for (int t = 0; t < 2; ++t) {
        int idx = tid + t * 256;          // 0..511: row=idx>>3, q=idx&7
        int r = idx >> 3, q = idx & 7;
        int e = e0 + r;
        float4 z = make_float4(0.f, 0.f, 0.f, 0.f);
        As4[r * 16 + q]     = (e < NE) ? ag[(size_t)e * 8 + q] : z;
        As4[r * 16 + 8 + q] = (e < NE) ? tg[(size_t)e * 8 + q] : z;
    }
    if (tid < 64) {
        int e = e0 + tid;
        s_src[tid] = (e < NE) ? eidx[e] : 0;
        s_dst[tid] = (e < NE) ? eidx[NE + e] : 0;
    }
    __syncthreads();

    float acc[8][4];
#pragma unroll
    for (int i = 0; i < 8; ++i) { acc[i][0] = acc[i][1] = acc[i][2] = acc[i][3] = 0.f; }

    const float4* Ar = (const float4*)(As + (ty * 8) * 64);
#pragma unroll 4
    for (int k4 = 0; k4 < 16; ++k4) {
        float4 a[8];
#pragma unroll
        for (int i = 0; i < 8; ++i) a[i] = Ar[i * 16 + k4];
#pragma unroll
        for (int kk = 0; kk < 4; ++kk) {
            const float* Bk = Bs + (k4 * 4 + kk) * 128 + tx;
            float b0 = Bk[0], b1 = Bk[32], b2 = Bk[64], b3 = Bk[96];
#pragma unroll
            for (int i = 0; i < 8; ++i) {
                float av = (kk == 0) ? a[i].x : (kk == 1) ? a[i].y : (kk == 2) ? a[i].z : a[i].w;
                acc[i][0] = fmaf(av, b0, acc[i][0]);
                acc[i][1] = fmaf(av, b1, acc[i][1]);
                acc[i][2] = fmaf(av, b2, acc[i][2]);
                acc[i][3] = fmaf(av, b3, acc[i][3]);
            }
        }
    }

#pragma unroll
    for (int i = 0; i < 8; ++i) {
        int li = ty * 8 + i;
        int e = e0 + li;
        if (e < NE) {
            const float* h = H1 + (size_t)s_src[li] * 128;
            float* ap = accum + (size_t)s_dst[li] * 128;
#pragma unroll
            for (int c = 0; c < 4; ++c) {
                int j = tx + 32 * c;
                float v = fmaxf(acc[i][c] + h[j], 0.f);
                atomicAdd(ap + j, v);
            }
        }
    }
}

// ---------------------------------------------------------------------------
// k3: out = dropout(relu(LN(acc @ W_lin + b_lin)))
// same GEMM tile as k1; LN per row via warp shfl (row fully inside one warp)
// ---------------------------------------------------------------------------
__global__ __launch_bounds__(256) void k3_update(
    const float* __restrict__ A, const float* __restrict__ W,
    const float* __restrict__ bias, const float* __restrict__ gamma,
    const float* __restrict__ beta, float* __restrict__ out)
{
    extern __shared__ float sm[];
    float* Ws = sm;
    float* As = sm + 128 * 128;
    const int tid = threadIdx.x, tx = tid & 31, ty = tid >> 5;
    const int row0 = blockIdx.x * 64;

    float4* Ws4 = (float4*)Ws;
    const float4* Wg = (const float4*)W;
#pragma unroll
    for (int t = 0; t < 16; ++t) Ws4[tid + t * 256] = Wg[tid + t * 256];

    float4* As4 = (float4*)As;
    const float4* Ag = (const float4*)A;
#pragma unroll
    for (int t = 0; t < 8; ++t) {
        int idx = tid + t * 256;
        int r = row0 + (idx >> 5);
        As4[idx] = (r < NN) ? Ag[(size_t)r * 32 + (idx & 31)]
                            : make_float4(0.f, 0.f, 0.f, 0.f);
    }
    __syncthreads();

    float acc[8][4];
#pragma unroll
    for (int i = 0; i < 8; ++i) { acc[i][0] = acc[i][1] = acc[i][2] = acc[i][3] = 0.f; }

    const float4* Ar = (const float4*)(As + (ty * 8) * 128);
#pragma unroll 4
    for (int k4 = 0; k4 < 32; ++k4) {
        float4 a[8];
#pragma unroll
        for (int i = 0; i < 8; ++i) a[i] = Ar[i * 32 + k4];
#pragma unroll
        for (int kk = 0; kk < 4; ++kk) {
            const float* Bk = Ws + (k4 * 4 + kk) * 128 + tx;
            float b0 = Bk[0], b1 = Bk[32], b2 = Bk[64], b3 = Bk[96];
#pragma unroll
            for (int i = 0; i < 8; ++i) {
                float av = (kk == 0) ? a[i].x : (kk == 1) ? a[i].y : (kk == 2) ? a[i].z : a[i].w;
                acc[i][0] = fmaf(av, b0, acc[i][0]);
                acc[i][1] = fmaf(av, b1, acc[i][1]);
                acc[i][2] = fmaf(av, b2, acc[i][2]);
                acc[i][3] = fmaf(av, b3, acc[i][3]);
            }
        }
    }

    float bb[4] = { bias[tx], bias[tx + 32], bias[tx + 64], bias[tx + 96] };
    float gm[4] = { gamma[tx], gamma[tx + 32], gamma[tx + 64], gamma[tx + 96] };
    float bt[4] = { beta[tx],  beta[tx + 32],  beta[tx + 64],  beta[tx + 96] };

#pragma unroll
    for (int i = 0; i < 8; ++i) {
        float v[4];
#pragma unroll
        for (int c = 0; c < 4; ++c) v[c] = acc[i][c] + bb[c];
        float s = v[0] + v[1] + v[2] + v[3];
#pragma unroll
        for (int off = 16; off; off >>= 1) s += __shfl_xor_sync(0xffffffffu, s, off);
        float mean = s * (1.0f / 128.0f);
        float d[4];
        float ss = 0.f;
#pragma unroll
        for (int c = 0; c < 4; ++c) { d[c] = v[c] - mean; ss += d[c] * d[c]; }
#pragma unroll
        for (int off = 16; off; off >>= 1) ss += __shfl_xor_sync(0xffffffffu, ss, off);
        float rstd = rsqrtf(ss * (1.0f / 128.0f) + 1e-5f);

        int r = row0 + ty * 8 + i;
        if (r < NN) {
            float* o = out + (size_t)r * 128;
#pragma unroll
            for (int c = 0; c < 4; ++c) {
                int j = tx + 32 * c;
                float y = d[c] * rstd * gm[c] + bt[c];
                y = fmaxf(y, 0.f);
                unsigned bits = threefry_bits((unsigned)(r * 128 + j));
                float u = __uint_as_float((bits >> 9) | 0x3F800000u) - 1.0f;
                o[j] = (u < 0.9f) ? (y / 0.9f) : 0.f;
            }
        }
    }
}

// ---------------------------------------------------------------------------
extern "C" void kernel_launch(void* const* d_in, const int* in_sizes, int n_in,
                              void* d_out, int out_size) {
    (void)in_sizes; (void)n_in; (void)out_size;
    const float* hidden   = (const float*)d_in[0];
    const int*   eidx     = (const int*)d_in[1];
    const float* eattr    = (const float*)d_in[2];
    const float* etime    = (const float*)d_in[3];
    const float* boundary = (const float*)d_in[4];
    const float* W_msg    = (const float*)d_in[5];
    const float* b_msg    = (const float*)d_in[6];
    const float* W_lin    = (const float*)d_in[7];
    const float* b_lin    = (const float*)d_in[8];
    const float* gamma    = (const float*)d_in[9];
    const float* beta     = (const float*)d_in[10];
    float* out = (float*)d_out;

    void* h1Ptr = nullptr;
    void* accPtr = nullptr;
    cudaGetSymbolAddress(&h1Ptr, g_H1);
    cudaGetSymbolAddress(&accPtr, g_acc);

    cudaFuncSetAttribute(k1_node_gemm, cudaFuncAttributeMaxDynamicSharedMemorySize, 98304);
    cudaFuncSetAttribute(k3_update,    cudaFuncAttributeMaxDynamicSharedMemorySize, 98304);
    cudaFuncSetAttribute(k2_edge,      cudaFuncAttributeMaxDynamicSharedMemorySize, 49664);

    // acc = boundary_condition (self-loop messages)
    cudaMemcpyAsync(accPtr, boundary, (size_t)NN * EMBD * sizeof(float),
                    cudaMemcpyDeviceToDevice, 0);

    // H1 = hidden @ W_msg[0:128] + b_msg   (per-node precompute)
    k1_node_gemm<<<(NN + 63) / 64, 256, 98304>>>(hidden, W_msg, b_msg, (float*)h1Ptr);

    // edge messages + scatter
    k2_edge<<<(NE + 63) / 64, 256, 49664>>>(eattr, etime, eidx, W_msg,
                                            (const float*)h1Ptr, (float*)accPtr);

    // node update: GEMM + LN + relu + threefry dropout
    k3_update<<<(NN + 63) / 64, 256, 98304>>>((const float*)accPtr, W_lin, b_lin,
                                              gamma, beta, out);
}

// round 4
// speedup vs baseline: 1.0935x; 1.0935x over previous
#include <cuda_runtime.h>
#include <cuda_bf16.h>
#include <cstdint>

#define NN  50000
#define EMBD 128
#define NE  500000

// scratch (allocation-free rule: __device__ globals)
__device__ __align__(16) float g_H1[NN * EMBD];
__device__ __align__(16) float g_acc[NN * EMBD];
// pre-split bf16 images of W23 = W_msg[128:192,:], plain row-major [64][128]
__device__ __align__(16) uint4 g_Bimg_hi[1024];   // 16KB
__device__ __align__(16) uint4 g_Bimg_lo[1024];   // 16KB

// ---------------------------------------------------------------------------
// threefry2x32, JAX partitionable mode. key=(0,42), counter=(0, flat),
// output = out0 ^ out1.
// ---------------------------------------------------------------------------
__device__ __forceinline__ unsigned tf_rotl(unsigned x, int r) {
    return __funnelshift_l(x, x, r);
}
__device__ __forceinline__ unsigned threefry_bits(unsigned flat) {
    unsigned x0 = 0u, x1 = flat;
    const unsigned ks0 = 0u, ks1 = 42u, ks2 = 0x1BD11BDAu ^ 0u ^ 42u;
    x0 += ks0; x1 += ks1;
#define TF_R(r) { x0 += x1; x1 = tf_rotl(x1, r); x1 ^= x0; }
    TF_R(13) TF_R(15) TF_R(26) TF_R(6)
    x0 += ks1; x1 += ks2 + 1u;
    TF_R(17) TF_R(29) TF_R(16) TF_R(24)
    x0 += ks2; x1 += ks0 + 2u;
    TF_R(13) TF_R(15) TF_R(26) TF_R(6)
    x0 += ks0; x1 += ks1 + 3u;
    TF_R(17) TF_R(29) TF_R(16) TF_R(24)
    x0 += ks1; x1 += ks2 + 4u;
    TF_R(13) TF_R(15) TF_R(26) TF_R(6)
    x0 += ks2; x1 += ks0 + 5u;
#undef TF_R
    return x0 ^ x1;
}

// ---------------------------------------------------------------------------
// baseline-PTX helpers (no 'a'-gated features!)
// ---------------------------------------------------------------------------
__device__ __forceinline__ uint32_t smem_u32(const void* p) {
    uint32_t a;
    asm("{ .reg .u64 t; cvta.to.shared.u64 t, %1; cvt.u32.u64 %0, t; }"
        : "=r"(a) : "l"(p));
    return a;
}
__device__ __forceinline__ void ldsm_x4(uint32_t addr, uint32_t& r0, uint32_t& r1,
                                        uint32_t& r2, uint32_t& r3) {
    asm volatile("ldmatrix.sync.aligned.m8n8.x4.shared.b16 {%0,%1,%2,%3}, [%4];"
                 : "=r"(r0), "=r"(r1), "=r"(r2), "=r"(r3) : "r"(addr));
}
__device__ __forceinline__ void ldsm_x4_t(uint32_t addr, uint32_t& r0, uint32_t& r1,
                                          uint32_t& r2, uint32_t& r3) {
    asm volatile("ldmatrix.sync.aligned.m8n8.x4.trans.shared.b16 {%0,%1,%2,%3}, [%4];"
                 : "=r"(r0), "=r"(r1), "=r"(r2), "=r"(r3) : "r"(addr));
}
__device__ __forceinline__ void mma16816(float* c, const uint32_t* a,
                                         uint32_t b0, uint32_t b1) {
    asm volatile(
        "mma.sync.aligned.m16n8k16.row.col.f32.bf16.bf16.f32 "
        "{%0,%1,%2,%3}, {%4,%5,%6,%7}, {%8,%9}, {%0,%1,%2,%3};"
        : "+f"(c[0]), "+f"(c[1]), "+f"(c[2]), "+f"(c[3])
        : "r"(a[0]), "r"(a[1]), "r"(a[2]), "r"(a[3]), "r"(b0), "r"(b1));
}
__device__ __forceinline__ void red_add_v2(float* p, float a, float b) {
    asm volatile("red.global.add.v2.f32 [%0], {%1, %2};"
                 :: "l"(p), "f"(a), "f"(b) : "memory");
}
__device__ __forceinline__ unsigned pack_bf2(__nv_bfloat16 a, __nv_bfloat16 b) {
    unsigned ua = (unsigned)__bfloat16_as_ushort(a);
    unsigned ub = (unsigned)__bfloat16_as_ushort(b);
    return ua | (ub << 16);
}

// ---------------------------------------------------------------------------
// k0: split W23 into hi/lo bf16 images, row-major [64][128]
// ---------------------------------------------------------------------------
__global__ __launch_bounds__(256) void k0_prep_w(const float* __restrict__ W_msg) {
    int idx = blockIdx.x * 256 + threadIdx.x;      // 0..8191
    float x = W_msg[128 * 128 + idx];
    __nv_bfloat16 h = __float2bfloat16(x);
    __nv_bfloat16 l = __float2bfloat16(x - __bfloat162float(h));
    ((__nv_bfloat16*)g_Bimg_hi)[idx] = h;
    ((__nv_bfloat16*)g_Bimg_lo)[idx] = l;
}

// ---------------------------------------------------------------------------
// k1: H1[N,128] = hidden[N,128] @ W_msg[0:128,:] + b_msg  (SIMT fp32)
// ---------------------------------------------------------------------------
__global__ __launch_bounds__(256) void k1_node_gemm(
    const float* __restrict__ A, const float* __restrict__ W,
    const float* __restrict__ bias, float* __restrict__ out)
{
    extern __shared__ float sm[];
    float* Ws = sm;               // 128x128
    float* As = sm + 128 * 128;   // 64x128
    const int tid = threadIdx.x, tx = tid & 31, ty = tid >> 5;
    const int row0 = blockIdx.x * 64;

    float4* Ws4 = (float4*)Ws;
    const float4* Wg = (const float4*)W;
#pragma unroll
    for (int t = 0; t < 16; ++t) Ws4[tid + t * 256] = Wg[tid + t * 256];

    float4* As4 = (float4*)As;
    const float4* Ag = (const float4*)A;
#pragma unroll
    for (int t = 0; t < 8; ++t) {
        int idx = tid + t * 256;
        int r = row0 + (idx >> 5);
        As4[idx] = (r < NN) ? Ag[(size_t)r * 32 + (idx & 31)]
                            : make_float4(0.f, 0.f, 0.f, 0.f);
    }
    __syncthreads();

    float acc[8][4];
#pragma unroll
    for (int i = 0; i < 8; ++i) { acc[i][0] = acc[i][1] = acc[i][2] = acc[i][3] = 0.f; }

    const float4* Ar = (const float4*)(As + (ty * 8) * 128);
#pragma unroll 4
    for (int k4 = 0; k4 < 32; ++k4) {
        float4 a[8];
#pragma unroll
        for (int i = 0; i < 8; ++i) a[i] = Ar[i * 32 + k4];
#pragma unroll
        for (int kk = 0; kk < 4; ++kk) {
            const float* Bk = Ws + (k4 * 4 + kk) * 128 + tx;
            float b0 = Bk[0], b1 = Bk[32], b2 = Bk[64], b3 = Bk[96];
#pragma unroll
            for (int i = 0; i < 8; ++i) {
                float av = (kk == 0) ? a[i].x : (kk == 1) ? a[i].y : (kk == 2) ? a[i].z : a[i].w;
                acc[i][0] = fmaf(av, b0, acc[i][0]);
                acc[i][1] = fmaf(av, b1, acc[i][1]);
                acc[i][2] = fmaf(av, b2, acc[i][2]);
                acc[i][3] = fmaf(av, b3, acc[i][3]);
            }
        }
    }
    float bb0 = bias[tx], bb1 = bias[tx + 32], bb2 = bias[tx + 64], bb3 = bias[tx + 96];
#pragma unroll
    for (int i = 0; i < 8; ++i) {
        int r = row0 + ty * 8 + i;
        if (r < NN) {
            float* o = out + (size_t)r * 128;
            o[tx]      = acc[i][0] + bb0;
            o[tx + 32] = acc[i][1] + bb1;
            o[tx + 64] = acc[i][2] + bb2;
            o[tx + 96] = acc[i][3] + bb3;
        }
    }
}

// ---------------------------------------------------------------------------
// k2: split-bf16 edge GEMM on mma.sync (HMMA) + gather/relu/scatter epilogue.
// CTA = 64 edges x 128 cols, 8 warps; warp = 16 edges x 64 cols.
// msg = relu(A@W23 + H1[src]);  red.v2 into acc[dst].
// ---------------------------------------------------------------------------
#define A_PITCH 144              // 64 bf16 + 8 pad = 144B per row
#define B_PITCH 272              // 128 bf16 + 8 pad = 272B per row
#define SM_AHI2 0                // 64 * 144 = 9216
#define SM_ALO2 9216
#define SM_BHI2 18432            // 64 * 272 = 17408
#define SM_BLO2 35840
#define SM_IDX2 53248            // s_src[64], s_dst[64]
#define SM_K2_TOTAL (53248 + 512)

__global__ __launch_bounds__(256) void k2_edge_mma(
    const float* __restrict__ eattr, const float* __restrict__ etime,
    const int* __restrict__ eidx, const float* __restrict__ H1,
    float* __restrict__ accum)
{
    extern __shared__ char smc[];
    const uint32_t sb = smem_u32(smc);
    const int tid = threadIdx.x;
    const int lane = tid & 31, w = tid >> 5;
    const int e0 = blockIdx.x * 64;
    int* s_src = (int*)(smc + SM_IDX2);
    int* s_dst = s_src + 64;

    // --- edge indices ---
    if (tid < 128) {
        int r = tid & 63;
        int e = e0 + r;
        int v = (e < NE) ? eidx[(tid < 64 ? 0 : NE) + e] : 0;
        if (tid < 64) s_src[r] = v; else s_dst[r] = v;
    }

    // --- B: copy pre-split images into padded smem rows ---
    {
        const uint4* bh = g_Bimg_hi;
        const uint4* bl = g_Bimg_lo;
#pragma unroll
        for (int t = 0; t < 4; ++t) {
            int idx = tid + t * 256;           // 0..1023, row=idx>>4, seg=idx&15
            int row = idx >> 4, seg = idx & 15;
            *(uint4*)(smc + SM_BHI2 + row * B_PITCH + seg * 16) = bh[idx];
            *(uint4*)(smc + SM_BLO2 + row * B_PITCH + seg * 16) = bl[idx];
        }
    }

    // --- A: load 16 f32 per thread (edge=tid>>2, quarter=tid&3), split hi/lo ---
    {
        int ed = tid >> 2, q = tid & 3;
        int e = e0 + ed;
        float xs[16];
        if (e < NE) {
            const float4* p = (q < 2) ? ((const float4*)(eattr + (size_t)e * 32) + q * 4)
                                      : ((const float4*)(etime + (size_t)e * 32) + (q - 2) * 4);
            float4 f0 = p[0], f1 = p[1], f2 = p[2], f3 = p[3];
            xs[0]=f0.x; xs[1]=f0.y; xs[2]=f0.z; xs[3]=f0.w;
            xs[4]=f1.x; xs[5]=f1.y; xs[6]=f1.z; xs[7]=f1.w;
            xs[8]=f2.x; xs[9]=f2.y; xs[10]=f2.z; xs[11]=f2.w;
            xs[12]=f3.x; xs[13]=f3.y; xs[14]=f3.z; xs[15]=f3.w;
        } else {
#pragma unroll
            for (int i = 0; i < 16; ++i) xs[i] = 0.f;
        }
        unsigned hw[8], lw[8];
#pragma unroll
        for (int j = 0; j < 8; ++j) {
            __nv_bfloat16 h0 = __float2bfloat16(xs[j * 2 + 0]);
            __nv_bfloat16 h1 = __float2bfloat16(xs[j * 2 + 1]);
            __nv_bfloat16 l0 = __float2bfloat16(xs[j * 2 + 0] - __bfloat162float(h0));
            __nv_bfloat16 l1 = __float2bfloat16(xs[j * 2 + 1] - __bfloat162float(h1));
            hw[j] = pack_bf2(h0, h1);
            lw[j] = pack_bf2(l0, l1);
        }
        char* dh = smc + SM_AHI2 + ed * A_PITCH + q * 32;
        char* dl = smc + SM_ALO2 + ed * A_PITCH + q * 32;
        *(uint4*)dh       = make_uint4(hw[0], hw[1], hw[2], hw[3]);
        *(uint4*)(dh + 16) = make_uint4(hw[4], hw[5], hw[6], hw[7]);
        *(uint4*)dl       = make_uint4(lw[0], lw[1], lw[2], lw[3]);
        *(uint4*)(dl + 16) = make_uint4(lw[4], lw[5], lw[6], lw[7]);
    }
    __syncthreads();

    const int m0 = (w >> 1) * 16;     // warp's edge-row base
    const int n0 = (w & 1) * 64;      // warp's col base

    // --- A fragments for all 4 k-steps, hi and lo ---
    uint32_t ahi[4][4], alo[4][4];
    {
        uint32_t rowA = (uint32_t)(m0 + (lane & 15));
        uint32_t colb = (uint32_t)((lane >> 4) * 16);
#pragma unroll
        for (int k = 0; k < 4; ++k) {
            uint32_t ad = sb + SM_AHI2 + rowA * A_PITCH + (uint32_t)k * 32 + colb;
            ldsm_x4(ad, ahi[k][0], ahi[k][1], ahi[k][2], ahi[k][3]);
            ldsm_x4(ad + (SM_ALO2 - SM_AHI2), alo[k][0], alo[k][1], alo[k][2], alo[k][3]);
        }
    }

    float acc[8][4];
#pragma unroll
    for (int i = 0; i < 8; ++i) { acc[i][0]=acc[i][1]=acc[i][2]=acc[i][3]=0.f; }

    const uint32_t rowB = (uint32_t)(lane & 15);
    const uint32_t colbB = (uint32_t)((lane >> 4) * 16);
#pragma unroll
    for (int p = 0; p < 4; ++p) {
#pragma unroll
        for (int k = 0; k < 4; ++k) {
            uint32_t bd = sb + SM_BHI2 + (k * 16 + rowB) * B_PITCH
                        + (uint32_t)(n0 + p * 16) * 2 + colbB;
            uint32_t bh0, bh1, bh2, bh3, bl0, bl1, bl2, bl3;
            ldsm_x4_t(bd, bh0, bh1, bh2, bh3);
            ldsm_x4_t(bd + (SM_BLO2 - SM_BHI2), bl0, bl1, bl2, bl3);
            mma16816(acc[p * 2],     ahi[k], bh0, bh1);
            mma16816(acc[p * 2],     ahi[k], bl0, bl1);
            mma16816(acc[p * 2],     alo[k], bh0, bh1);
            mma16816(acc[p * 2 + 1], ahi[k], bh2, bh3);
            mma16816(acc[p * 2 + 1], ahi[k], bl2, bl3);
            mma16816(acc[p * 2 + 1], alo[k], bh2, bh3);
        }
    }

    // --- epilogue: gather H1[src], relu, scatter red.v2 into acc[dst] ---
    const int r0 = m0 + (lane >> 2), r1 = r0 + 8;
    const bool v0 = (e0 + r0) < NE, v1 = (e0 + r1) < NE;
    const float* h0p = g_H1 == H1 ? H1 + (size_t)s_src[r0] * 128
                                  : H1 + (size_t)s_src[r0] * 128;  // keep simple
    const float* h1p = H1 + (size_t)s_src[r1] * 128;
    float* a0p = accum + (size_t)s_dst[r0] * 128;
    float* a1p = accum + (size_t)s_dst[r1] * 128;
#pragma unroll
    for (int nt = 0; nt < 8; ++nt) {
        int j = n0 + nt * 8 + (lane & 3) * 2;
        if (v0) {
            float2 h = *(const float2*)(h0p + j);
            red_add_v2(a0p + j, fmaxf(acc[nt][0] + h.x, 0.f),
                                fmaxf(acc[nt][1] + h.y, 0.f));
        }
        if (v1) {
            float2 h = *(const float2*)(h1p + j);
            red_add_v2(a1p + j, fmaxf(acc[nt][2] + h.x, 0.f),
                                fmaxf(acc[nt][3] + h.y, 0.f));
        }
    }
}

// ---------------------------------------------------------------------------
// k3: out = dropout(relu(LN(acc @ W_lin + b_lin)))   (SIMT fp32)
// ---------------------------------------------------------------------------
__global__ __launch_bounds__(256) void k3_update(
    const float* __restrict__ A, const float* __restrict__ W,
    const float* __restrict__ bias, const float* __restrict__ gamma,
    const float* __restrict__ beta, float* __restrict__ out)
{
    extern __shared__ float sm[];
    float* Ws = sm;
    float* As = sm + 128 * 128;
    const int tid = threadIdx.x, tx = tid & 31, ty = tid >> 5;
    const int row0 = blockIdx.x * 64;

    float4* Ws4 = (float4*)Ws;
    const float4* Wg = (const float4*)W;
#pragma unroll
    for (int t = 0; t < 16; ++t) Ws4[tid + t * 256] = Wg[tid + t * 256];

    float4* As4 = (float4*)As;
    const float4* Ag = (const float4*)A;
#pragma unroll
    for (int t = 0; t < 8; ++t) {
        int idx = tid + t * 256;
        int r = row0 + (idx >> 5);
        As4[idx] = (r < NN) ? Ag[(size_t)r * 32 + (idx & 31)]
                            : make_float4(0.f, 0.f, 0.f, 0.f);
    }
    __syncthreads();

    float acc[8][4];
#pragma unroll
    for (int i = 0; i < 8; ++i) { acc[i][0] = acc[i][1] = acc[i][2] = acc[i][3] = 0.f; }

    const float4* Ar = (const float4*)(As + (ty * 8) * 128);
#pragma unroll 4
    for (int k4 = 0; k4 < 32; ++k4) {
        float4 a[8];
#pragma unroll
        for (int i = 0; i < 8; ++i) a[i] = Ar[i * 32 + k4];
#pragma unroll
        for (int kk = 0; kk < 4; ++kk) {
            const float* Bk = Ws + (k4 * 4 + kk) * 128 + tx;
            float b0 = Bk[0], b1 = Bk[32], b2 = Bk[64], b3 = Bk[96];
#pragma unroll
            for (int i = 0; i < 8; ++i) {
                float av = (kk == 0) ? a[i].x : (kk == 1) ? a[i].y : (kk == 2) ? a[i].z : a[i].w;
                acc[i][0] = fmaf(av, b0, acc[i][0]);
                acc[i][1] = fmaf(av, b1, acc[i][1]);
                acc[i][2] = fmaf(av, b2, acc[i][2]);
                acc[i][3] = fmaf(av, b3, acc[i][3]);
            }
        }
    }

    float bb[4] = { bias[tx], bias[tx + 32], bias[tx + 64], bias[tx + 96] };
    float gm[4] = { gamma[tx], gamma[tx + 32], gamma[tx + 64], gamma[tx + 96] };
    float bt[4] = { beta[tx],  beta[tx + 32],  beta[tx + 64],  beta[tx + 96] };

#pragma unroll
    for (int i = 0; i < 8; ++i) {
        float v[4];
#pragma unroll
        for (int c = 0; c < 4; ++c) v[c] = acc[i][c] + bb[c];
        float s = v[0] + v[1] + v[2] + v[3];
#pragma unroll
        for (int off = 16; off; off >>= 1) s += __shfl_xor_sync(0xffffffffu, s, off);
        float mean = s * (1.0f / 128.0f);
        float d[4];
        float ss = 0.f;
#pragma unroll
        for (int c = 0; c < 4; ++c) { d[c] = v[c] - mean; ss += d[c] * d[c]; }
#pragma unroll
        for (int off = 16; off; off >>= 1) ss += __shfl_xor_sync(0xffffffffu, ss, off);
        float rstd = rsqrtf(ss * (1.0f / 128.0f) + 1e-5f);

        int r = row0 + ty * 8 + i;
        if (r < NN) {
            float* o = out + (size_t)r * 128;
#pragma unroll
            for (int c = 0; c < 4; ++c) {
                int j = tx + 32 * c;
                float y = d[c] * rstd * gm[c] + bt[c];
                y = fmaxf(y, 0.f);
                unsigned bits = threefry_bits((unsigned)(r * 128 + j));
                float u = __uint_as_float((bits >> 9) | 0x3F800000u) - 1.0f;
                o[j] = (u < 0.9f) ? (y / 0.9f) : 0.f;
            }
        }
    }
}

// ---------------------------------------------------------------------------
extern "C" void kernel_launch(void* const* d_in, const int* in_sizes, int n_in,
                              void* d_out, int out_size) {
    (void)in_sizes; (void)n_in; (void)out_size;
    const float* hidden   = (const float*)d_in[0];
    const int*   eidx     = (const int*)d_in[1];
    const float* eattr    = (const float*)d_in[2];
    const float* etime    = (const float*)d_in[3];
    const float* boundary = (const float*)d_in[4];
    const float* W_msg    = (const float*)d_in[5];
    const float* b_msg    = (const float*)d_in[6];
    const float* W_lin    = (const float*)d_in[7];
    const float* b_lin    = (const float*)d_in[8];
    const float* gamma    = (const float*)d_in[9];
    const float* beta     = (const float*)d_in[10];
    float* out = (float*)d_out;

    void* h1Ptr = nullptr;
    void* accPtr = nullptr;
    cudaGetSymbolAddress(&h1Ptr, g_H1);
    cudaGetSymbolAddress(&accPtr, g_acc);

    cudaFuncSetAttribute(k1_node_gemm, cudaFuncAttributeMaxDynamicSharedMemorySize, 98304);
    cudaFuncSetAttribute(k3_update,    cudaFuncAttributeMaxDynamicSharedMemorySize, 98304);
    cudaFuncSetAttribute(k2_edge_mma,  cudaFuncAttributeMaxDynamicSharedMemorySize, SM_K2_TOTAL);

    // acc = boundary_condition (self-loop messages)
    cudaMemcpyAsync(accPtr, boundary, (size_t)NN * EMBD * sizeof(float),
                    cudaMemcpyDeviceToDevice, 0);

    // prep: split W23 into bf16 hi/lo images
    k0_prep_w<<<32, 256>>>(W_msg);

    // H1 = hidden @ W_msg[0:128] + b_msg
    k1_node_gemm<<<(NN + 63) / 64, 256, 98304>>>(hidden, W_msg, b_msg, (float*)h1Ptr);

    // edge messages (HMMA split-bf16) + scatter
    k2_edge_mma<<<(NE + 63) / 64, 256, SM_K2_TOTAL>>>(eattr, etime, eidx,
                                                      (const float*)h1Ptr, (float*)accPtr);

    // node update: GEMM + LN + relu + threefry dropout
    k3_update<<<(NN + 63) / 64, 256, 98304>>>((const float*)accPtr, W_lin, b_lin,
                                              gamma, beta, out);
}

// round 5
// speedup vs baseline: 1.1210x; 1.0251x over previous
#include <cuda_runtime.h>
#include <cuda_bf16.h>
#include <cstdint>

#define NN  50000
#define EMBD 128
#define NE  500000

// scratch (allocation-free rule: __device__ globals)
__device__ __align__(16) float g_H1[NN * EMBD];
__device__ __align__(16) float g_acc[NN * EMBD];
// pre-split bf16 images (row-major [k][n])
__device__ __align__(16) uint4 g_W1img_hi[2048];  // 32KB, W_msg[0:128,:]
__device__ __align__(16) uint4 g_W1img_lo[2048];
__device__ __align__(16) uint4 g_Bimg_hi[1024];   // 16KB, W_msg[128:192,:]
__device__ __align__(16) uint4 g_Bimg_lo[1024];

// ---------------------------------------------------------------------------
// threefry2x32, JAX partitionable mode. key=(0,42), counter=(0, flat),
// output = out0 ^ out1.
// ---------------------------------------------------------------------------
__device__ __forceinline__ unsigned tf_rotl(unsigned x, int r) {
    return __funnelshift_l(x, x, r);
}
__device__ __forceinline__ unsigned threefry_bits(unsigned flat) {
    unsigned x0 = 0u, x1 = flat;
    const unsigned ks0 = 0u, ks1 = 42u, ks2 = 0x1BD11BDAu ^ 0u ^ 42u;
    x0 += ks0; x1 += ks1;
#define TF_R(r) { x0 += x1; x1 = tf_rotl(x1, r); x1 ^= x0; }
    TF_R(13) TF_R(15) TF_R(26) TF_R(6)
    x0 += ks1; x1 += ks2 + 1u;
    TF_R(17) TF_R(29) TF_R(16) TF_R(24)
    x0 += ks2; x1 += ks0 + 2u;
    TF_R(13) TF_R(15) TF_R(26) TF_R(6)
    x0 += ks0; x1 += ks1 + 3u;
    TF_R(17) TF_R(29) TF_R(16) TF_R(24)
    x0 += ks1; x1 += ks2 + 4u;
    TF_R(13) TF_R(15) TF_R(26) TF_R(6)
    x0 += ks2; x1 += ks0 + 5u;
#undef TF_R
    return x0 ^ x1;
}

// ---------------------------------------------------------------------------
// baseline-PTX helpers (no 'a'-gated features)
// ---------------------------------------------------------------------------
__device__ __forceinline__ uint32_t smem_u32(const void* p) {
    uint32_t a;
    asm("{ .reg .u64 t; cvta.to.shared.u64 t, %1; cvt.u32.u64 %0, t; }"
        : "=r"(a) : "l"(p));
    return a;
}
__device__ __forceinline__ void ldsm_x4(uint32_t addr, uint32_t* r) {
    asm volatile("ldmatrix.sync.aligned.m8n8.x4.shared.b16 {%0,%1,%2,%3}, [%4];"
                 : "=r"(r[0]), "=r"(r[1]), "=r"(r[2]), "=r"(r[3]) : "r"(addr));
}
__device__ __forceinline__ void ldsm_x4_t(uint32_t addr, uint32_t& r0, uint32_t& r1,
                                          uint32_t& r2, uint32_t& r3) {
    asm volatile("ldmatrix.sync.aligned.m8n8.x4.trans.shared.b16 {%0,%1,%2,%3}, [%4];"
                 : "=r"(r0), "=r"(r1), "=r"(r2), "=r"(r3) : "r"(addr));
}
__device__ __forceinline__ void mma16816(float* c, const uint32_t* a,
                                         uint32_t b0, uint32_t b1) {
    asm volatile(
        "mma.sync.aligned.m16n8k16.row.col.f32.bf16.bf16.f32 "
        "{%0,%1,%2,%3}, {%4,%5,%6,%7}, {%8,%9}, {%0,%1,%2,%3};"
        : "+f"(c[0]), "+f"(c[1]), "+f"(c[2]), "+f"(c[3])
        : "r"(a[0]), "r"(a[1]), "r"(a[2]), "r"(a[3]), "r"(b0), "r"(b1));
}
__device__ __forceinline__ void red_add_v2(float* p, float a, float b) {
    asm volatile("red.global.add.v2.f32 [%0], {%1, %2};"
                 :: "l"(p), "f"(a), "f"(b) : "memory");
}
__device__ __forceinline__ unsigned pack_bf2(__nv_bfloat16 a, __nv_bfloat16 b) {
    unsigned ua = (unsigned)__bfloat16_as_ushort(a);
    unsigned ub = (unsigned)__bfloat16_as_ushort(b);
    return ua | (ub << 16);
}
__device__ __forceinline__ void split_store(char* dh, char* dl, const float* xs) {
    unsigned hw[8], lw[8];
#pragma unroll
    for (int j = 0; j < 8; ++j) {
        __nv_bfloat16 h0 = __float2bfloat16(xs[j * 2 + 0]);
        __nv_bfloat16 h1 = __float2bfloat16(xs[j * 2 + 1]);
        __nv_bfloat16 l0 = __float2bfloat16(xs[j * 2 + 0] - __bfloat162float(h0));
        __nv_bfloat16 l1 = __float2bfloat16(xs[j * 2 + 1] - __bfloat162float(h1));
        hw[j] = pack_bf2(h0, h1);
        lw[j] = pack_bf2(l0, l1);
    }
    *(uint4*)dh        = make_uint4(hw[0], hw[1], hw[2], hw[3]);
    *(uint4*)(dh + 16) = make_uint4(hw[4], hw[5], hw[6], hw[7]);
    *(uint4*)dl        = make_uint4(lw[0], lw[1], lw[2], lw[3]);
    *(uint4*)(dl + 16) = make_uint4(lw[4], lw[5], lw[6], lw[7]);
}

// ---------------------------------------------------------------------------
// k0: split W_msg into hi/lo bf16 images (W1: 16384 elems, W23: 8192 elems)
// ---------------------------------------------------------------------------
__global__ __launch_bounds__(256) void k0_prep_w(const float* __restrict__ W_msg) {
    int idx = blockIdx.x * 256 + threadIdx.x;      // 0..24575
    float x = W_msg[idx];
    __nv_bfloat16 h = __float2bfloat16(x);
    __nv_bfloat16 l = __float2bfloat16(x - __bfloat162float(h));
    if (idx < 16384) {
        ((__nv_bfloat16*)g_W1img_hi)[idx] = h;
        ((__nv_bfloat16*)g_W1img_lo)[idx] = l;
    } else {
        ((__nv_bfloat16*)g_Bimg_hi)[idx - 16384] = h;
        ((__nv_bfloat16*)g_Bimg_lo)[idx - 16384] = l;
    }
}

// ---------------------------------------------------------------------------
// k1: H1[N,128] = hidden @ W1 + b_msg via split-bf16 HMMA.
// CTA = 64 rows x 128 cols, 256 thr, 8 warps (2m x 4n), warp = 32r x 32c.
// ---------------------------------------------------------------------------
#define K1_APITCH 272
#define K1_BPITCH 272
#define K1_AHI 0
#define K1_ALO 17408
#define K1_BHI 34816
#define K1_BLO 69632
#define K1_SMEM 104448

__global__ __launch_bounds__(256) void k1_node_hmma(
    const float* __restrict__ A, const float* __restrict__ bias,
    float* __restrict__ out)
{
    extern __shared__ char smc[];
    const uint32_t sb = smem_u32(smc);
    const int tid = threadIdx.x;
    const int lane = tid & 31, w = tid >> 5;
    const int row0 = blockIdx.x * 64;

    // B: copy pre-split W1 images (2048 uint4 each)
    {
        const uint4* bh = g_W1img_hi;
        const uint4* bl = g_W1img_lo;
#pragma unroll
        for (int t = 0; t < 8; ++t) {
            int idx = tid + t * 256;            // row=idx>>4 (0..127), seg=idx&15
            int row = idx >> 4, seg = idx & 15;
            *(uint4*)(smc + K1_BHI + row * K1_BPITCH + seg * 16) = bh[idx];
            *(uint4*)(smc + K1_BLO + row * K1_BPITCH + seg * 16) = bl[idx];
        }
    }
    // A: 64 rows x 128 f32; thread: row=tid>>2, q=tid&3 -> cols q*32..q*32+31
    {
        int r = tid >> 2, q = tid & 3;
        int gr = row0 + r;
        float xs[32];
        if (gr < NN) {
            const float4* p = (const float4*)(A + (size_t)gr * 128 + q * 32);
#pragma unroll
            for (int i = 0; i < 8; ++i) {
                float4 f = p[i];
                xs[i*4+0]=f.x; xs[i*4+1]=f.y; xs[i*4+2]=f.z; xs[i*4+3]=f.w;
            }
        } else {
#pragma unroll
            for (int i = 0; i < 32; ++i) xs[i] = 0.f;
        }
        split_store(smc + K1_AHI + r * K1_APITCH + q * 64,
                    smc + K1_ALO + r * K1_APITCH + q * 64, xs);
        split_store(smc + K1_AHI + r * K1_APITCH + q * 64 + 32,
                    smc + K1_ALO + r * K1_APITCH + q * 64 + 32, xs + 16);
    }
    __syncthreads();

    const int m0 = (w >> 2) * 32;     // 0 or 32
    const int n0 = (w & 3) * 32;

    float acc[2][4][4];
#pragma unroll
    for (int a = 0; a < 2; ++a)
#pragma unroll
        for (int b = 0; b < 4; ++b)
#pragma unroll
            for (int c = 0; c < 4; ++c) acc[a][b][c] = 0.f;

    const uint32_t arow = (uint32_t)(lane & 15);
    const uint32_t acol = (uint32_t)((lane >> 4) * 16);

    // pass 1: ahi x (bhi + blo)
#pragma unroll
    for (int k = 0; k < 8; ++k) {
        uint32_t a0[4], a1[4];
        uint32_t ad = sb + K1_AHI + (uint32_t)(m0 + arow) * K1_APITCH + k * 32 + acol;
        ldsm_x4(ad, a0);
        ldsm_x4(ad + 16 * K1_APITCH, a1);
#pragma unroll
        for (int p = 0; p < 2; ++p) {
            uint32_t bd = sb + K1_BHI + (uint32_t)(k * 16 + arow) * K1_BPITCH
                        + (uint32_t)(n0 + p * 16) * 2 + acol;
            uint32_t h0,h1,h2,h3, l0,l1,l2,l3;
            ldsm_x4_t(bd, h0, h1, h2, h3);
            ldsm_x4_t(bd + (K1_BLO - K1_BHI), l0, l1, l2, l3);
            mma16816(acc[0][p*2],   a0, h0, h1);
            mma16816(acc[0][p*2+1], a0, h2, h3);
            mma16816(acc[1][p*2],   a1, h0, h1);
            mma16816(acc[1][p*2+1], a1, h2, h3);
            mma16816(acc[0][p*2],   a0, l0, l1);
            mma16816(acc[0][p*2+1], a0, l2, l3);
            mma16816(acc[1][p*2],   a1, l0, l1);
            mma16816(acc[1][p*2+1], a1, l2, l3);
        }
    }
    // pass 2: alo x bhi
#pragma unroll
    for (int k = 0; k < 8; ++k) {
        uint32_t a0[4], a1[4];
        uint32_t ad = sb + K1_ALO + (uint32_t)(m0 + arow) * K1_APITCH + k * 32 + acol;
        ldsm_x4(ad, a0);
        ldsm_x4(ad + 16 * K1_APITCH, a1);
#pragma unroll
        for (int p = 0; p < 2; ++p) {
            uint32_t bd = sb + K1_BHI + (uint32_t)(k * 16 + arow) * K1_BPITCH
                        + (uint32_t)(n0 + p * 16) * 2 + acol;
            uint32_t h0,h1,h2,h3;
            ldsm_x4_t(bd, h0, h1, h2, h3);
            mma16816(acc[0][p*2],   a0, h0, h1);
            mma16816(acc[0][p*2+1], a0, h2, h3);
            mma16816(acc[1][p*2],   a1, h0, h1);
            mma16816(acc[1][p*2+1], a1, h2, h3);
        }
    }

    // epilogue: + bias, store
#pragma unroll
    for (int mt = 0; mt < 2; ++mt) {
#pragma unroll
        for (int half = 0; half < 2; ++half) {
            int r = row0 + m0 + mt * 16 + (lane >> 2) + half * 8;
            if (r < NN) {
                float* o = out + (size_t)r * 128;
#pragma unroll
                for (int nt = 0; nt < 4; ++nt) {
                    int j = n0 + nt * 8 + (lane & 3) * 2;
                    float2 b2 = *(const float2*)(bias + j);
                    float2 v;
                    v.x = acc[mt][nt][half * 2 + 0] + b2.x;
                    v.y = acc[mt][nt][half * 2 + 1] + b2.y;
                    *(float2*)(o + j) = v;
                }
            }
        }
    }
}

// ---------------------------------------------------------------------------
// k2: split-bf16 edge GEMM (HMMA, fragment-reuse layout).
// CTA = 128 edges x 128 cols, 512 thr, 16 warps (4m x 4n), warp = 32e x 32c.
// msg = relu(A@W23 + H1[src]);  red.v2 into acc[dst].
// ---------------------------------------------------------------------------
#define K2_APITCH 144
#define K2_BPITCH 272
#define K2_AHI 0
#define K2_ALO 18432
#define K2_BHI 36864
#define K2_BLO 54272
#define K2_IDX 71680
#define K2_SMEM 72704

__global__ __launch_bounds__(512) void k2_edge_mma(
    const float* __restrict__ eattr, const float* __restrict__ etime,
    const int* __restrict__ eidx, const float* __restrict__ H1,
    float* __restrict__ accum)
{
    extern __shared__ char smc[];
    const uint32_t sb = smem_u32(smc);
    const int tid = threadIdx.x;
    const int lane = tid & 31, w = tid >> 5;
    const int e0 = blockIdx.x * 128;
    int* s_src = (int*)(smc + K2_IDX);
    int* s_dst = s_src + 128;

    // edge indices
    if (tid < 256) {
        int r = tid & 127;
        int e = e0 + r;
        int v = (e < NE) ? eidx[(tid < 128 ? 0 : NE) + e] : 0;
        if (tid < 128) s_src[r] = v; else s_dst[r] = v;
    }
    // B: copy pre-split W23 images (1024 uint4 each)
    {
        const uint4* bh = g_Bimg_hi;
        const uint4* bl = g_Bimg_lo;
#pragma unroll
        for (int t = 0; t < 2; ++t) {
            int idx = tid + t * 512;            // row=idx>>4 (0..63), seg=idx&15
            int row = idx >> 4, seg = idx & 15;
            *(uint4*)(smc + K2_BHI + row * K2_BPITCH + seg * 16) = bh[idx];
            *(uint4*)(smc + K2_BLO + row * K2_BPITCH + seg * 16) = bl[idx];
        }
    }
    // A: edge features, 128 edges x 64 f32; thread: ed=tid>>2, q=tid&3 (16 floats)
    {
        int ed = tid >> 2, q = tid & 3;
        int e = e0 + ed;
        float xs[16];
        if (e < NE) {
            const float4* p = (q < 2) ? ((const float4*)(eattr + (size_t)e * 32) + q * 4)
                                      : ((const float4*)(etime + (size_t)e * 32) + (q - 2) * 4);
            float4 f0 = p[0], f1 = p[1], f2 = p[2], f3 = p[3];
            xs[0]=f0.x; xs[1]=f0.y; xs[2]=f0.z; xs[3]=f0.w;
            xs[4]=f1.x; xs[5]=f1.y; xs[6]=f1.z; xs[7]=f1.w;
            xs[8]=f2.x; xs[9]=f2.y; xs[10]=f2.z; xs[11]=f2.w;
            xs[12]=f3.x; xs[13]=f3.y; xs[14]=f3.z; xs[15]=f3.w;
        } else {
#pragma unroll
            for (int i = 0; i < 16; ++i) xs[i] = 0.f;
        }
        split_store(smc + K2_AHI + ed * K2_APITCH + q * 32,
                    smc + K2_ALO + ed * K2_APITCH + q * 32, xs);
    }
    __syncthreads();

    const int m0 = (w >> 2) * 32;     // edge-row base (0,32,64,96)
    const int n0 = (w & 3) * 32;      // col base

    float acc[2][4][4];
#pragma unroll
    for (int a = 0; a < 2; ++a)
#pragma unroll
        for (int b = 0; b < 4; ++b)
#pragma unroll
            for (int c = 0; c < 4; ++c) acc[a][b][c] = 0.f;

    const uint32_t arow = (uint32_t)(lane & 15);
    const uint32_t acol = (uint32_t)((lane >> 4) * 16);

    // pass 1: ahi x (bhi + blo)
#pragma unroll
    for (int k = 0; k < 4; ++k) {
        uint32_t a0[4], a1[4];
        uint32_t ad = sb + K2_AHI + (uint32_t)(m0 + arow) * K2_APITCH + k * 32 + acol;
        ldsm_x4(ad, a0);
        ldsm_x4(ad + 16 * K2_APITCH, a1);
#pragma unroll
        for (int p = 0; p < 2; ++p) {
            uint32_t bd = sb + K2_BHI + (uint32_t)(k * 16 + arow) * K2_BPITCH
                        + (uint32_t)(n0 + p * 16) * 2 + acol;
            uint32_t h0,h1,h2,h3, l0,l1,l2,l3;
            ldsm_x4_t(bd, h0, h1, h2, h3);
            ldsm_x4_t(bd + (K2_BLO - K2_BHI), l0, l1, l2, l3);
            mma16816(acc[0][p*2],   a0, h0, h1);
            mma16816(acc[0][p*2+1], a0, h2, h3);
            mma16816(acc[1][p*2],   a1, h0, h1);
            mma16816(acc[1][p*2+1], a1, h2, h3);
            mma16816(acc[0][p*2],   a0, l0, l1);
            mma16816(acc[0][p*2+1], a0, l2, l3);
            mma16816(acc[1][p*2],   a1, l0, l1);
            mma16816(acc[1][p*2+1], a1, l2, l3);
        }
    }
    // pass 2: alo x bhi
#pragma unroll
    for (int k = 0; k < 4; ++k) {
        uint32_t a0[4], a1[4];
        uint32_t ad = sb + K2_ALO + (uint32_t)(m0 + arow) * K2_APITCH + k * 32 + acol;
        ldsm_x4(ad, a0);
        ldsm_x4(ad + 16 * K2_APITCH, a1);
#pragma unroll
        for (int p = 0; p < 2; ++p) {
            uint32_t bd = sb + K2_BHI + (uint32_t)(k * 16 + arow) * K2_BPITCH
                        + (uint32_t)(n0 + p * 16) * 2 + acol;
            uint32_t h0,h1,h2,h3;
            ldsm_x4_t(bd, h0, h1, h2, h3);
            mma16816(acc[0][p*2],   a0, h0, h1);
            mma16816(acc[0][p*2+1], a0, h2, h3);
            mma16816(acc[1][p*2],   a1, h0, h1);
            mma16816(acc[1][p*2+1], a1, h2, h3);
        }
    }

    // epilogue: gather H1[src], relu, scatter red.v2 into acc[dst]
#pragma unroll
    for (int mt = 0; mt < 2; ++mt) {
#pragma unroll
        for (int half = 0; half < 2; ++half) {
            int r = m0 + mt * 16 + (lane >> 2) + half * 8;
            if (e0 + r < NE) {
                const float* hp = H1 + (size_t)s_src[r] * 128;
                float* ap = accum + (size_t)s_dst[r] * 128;
#pragma unroll
                for (int nt = 0; nt < 4; ++nt) {
                    int j = n0 + nt * 8 + (lane & 3) * 2;
                    float2 h = *(const float2*)(hp + j);
                    red_add_v2(ap + j,
                               fmaxf(acc[mt][nt][half * 2 + 0] + h.x, 0.f),
                               fmaxf(acc[mt][nt][half * 2 + 1] + h.y, 0.f));
                }
            }
        }
    }
}

// ---------------------------------------------------------------------------
// k3: out = dropout(relu(LN(acc @ W_lin + b_lin)))   (SIMT fp32)
// ---------------------------------------------------------------------------
__global__ __launch_bounds__(256) void k3_update(
    const float* __restrict__ A, const float* __restrict__ W,
    const float* __restrict__ bias, const float* __restrict__ gamma,
    const float* __restrict__ beta, float* __restrict__ out)
{
    extern __shared__ float sm[];
    float* Ws = sm;
    float* As = sm + 128 * 128;
    const int tid = threadIdx.x, tx = tid & 31, ty = tid >> 5;
    const int row0 = blockIdx.x * 64;

    float4* Ws4 = (float4*)Ws;
    const float4* Wg = (const float4*)W;
#pragma unroll
    for (int t = 0; t < 16; ++t) Ws4[tid + t * 256] = Wg[tid + t * 256];

    float4* As4 = (float4*)As;
    const float4* Ag = (const float4*)A;
#pragma unroll
    for (int t = 0; t < 8; ++t) {
        int idx = tid + t * 256;
        int r = row0 + (idx >> 5);
        As4[idx] = (r < NN) ? Ag[(size_t)r * 32 + (idx & 31)]
                            : make_float4(0.f, 0.f, 0.f, 0.f);
    }
    __syncthreads();

    float acc[8][4];
#pragma unroll
    for (int i = 0; i < 8; ++i) { acc[i][0] = acc[i][1] = acc[i][2] = acc[i][3] = 0.f; }

    const float4* Ar = (const float4*)(As + (ty * 8) * 128);
#pragma unroll 4
    for (int k4 = 0; k4 < 32; ++k4) {
        float4 a[8];
#pragma unroll
        for (int i = 0; i < 8; ++i) a[i] = Ar[i * 32 + k4];
#pragma unroll
        for (int kk = 0; kk < 4; ++kk) {
            const float* Bk = Ws + (k4 * 4 + kk) * 128 + tx;
            float b0 = Bk[0], b1 = Bk[32], b2 = Bk[64], b3 = Bk[96];
#pragma unroll
            for (int i = 0; i < 8; ++i) {
                float av = (kk == 0) ? a[i].x : (kk == 1) ? a[i].y : (kk == 2) ? a[i].z : a[i].w;
                acc[i][0] = fmaf(av, b0, acc[i][0]);
                acc[i][1] = fmaf(av, b1, acc[i][1]);
                acc[i][2] = fmaf(av, b2, acc[i][2]);
                acc[i][3] = fmaf(av, b3, acc[i][3]);
            }
        }
    }

    float bb[4] = { bias[tx], bias[tx + 32], bias[tx + 64], bias[tx + 96] };
    float gm[4] = { gamma[tx], gamma[tx + 32], gamma[tx + 64], gamma[tx + 96] };
    float bt[4] = { beta[tx],  beta[tx + 32],  beta[tx + 64],  beta[tx + 96] };

#pragma unroll
    for (int i = 0; i < 8; ++i) {
        float v[4];
#pragma unroll
        for (int c = 0; c < 4; ++c) v[c] = acc[i][c] + bb[c];
        float s = v[0] + v[1] + v[2] + v[3];
#pragma unroll
        for (int off = 16; off; off >>= 1) s += __shfl_xor_sync(0xffffffffu, s, off);
        float mean = s * (1.0f / 128.0f);
        float d[4];
        float ss = 0.f;
#pragma unroll
        for (int c = 0; c < 4; ++c) { d[c] = v[c] - mean; ss += d[c] * d[c]; }
#pragma unroll
        for (int off = 16; off; off >>= 1) ss += __shfl_xor_sync(0xffffffffu, ss, off);
        float rstd = rsqrtf(ss * (1.0f / 128.0f) + 1e-5f);

        int r = row0 + ty * 8 + i;
        if (r < NN) {
            float* o = out + (size_t)r * 128;
#pragma unroll
            for (int c = 0; c < 4; ++c) {
                int j = tx + 32 * c;
                float y = d[c] * rstd * gm[c] + bt[c];
                y = fmaxf(y, 0.f);
                unsigned bits = threefry_bits((unsigned)(r * 128 + j));
                float u = __uint_as_float((bits >> 9) | 0x3F800000u) - 1.0f;
                o[j] = (u < 0.9f) ? (y / 0.9f) : 0.f;
            }
        }
    }
}

// ---------------------------------------------------------------------------
extern "C" void kernel_launch(void* const* d_in, const int* in_sizes, int n_in,
                              void* d_out, int out_size) {
    (void)in_sizes; (void)n_in; (void)out_size;
    const float* hidden   = (const float*)d_in[0];
    const int*   eidx     = (const int*)d_in[1];
    const float* eattr    = (const float*)d_in[2];
    const float* etime    = (const float*)d_in[3];
    const float* boundary = (const float*)d_in[4];
    const float* W_msg    = (const float*)d_in[5];
    const float* b_msg    = (const float*)d_in[6];
    const float* W_lin    = (const float*)d_in[7];
    const float* b_lin    = (const float*)d_in[8];
    const float* gamma    = (const float*)d_in[9];
    const float* beta     = (const float*)d_in[10];
    float* out = (float*)d_out;

    void* h1Ptr = nullptr;
    void* accPtr = nullptr;
    cudaGetSymbolAddress(&h1Ptr, g_H1);
    cudaGetSymbolAddress(&accPtr, g_acc);

    cudaFuncSetAttribute(k1_node_hmma, cudaFuncAttributeMaxDynamicSharedMemorySize, K1_SMEM);
    cudaFuncSetAttribute(k2_edge_mma,  cudaFuncAttributeMaxDynamicSharedMemorySize, K2_SMEM);
    cudaFuncSetAttribute(k3_update,    cudaFuncAttributeMaxDynamicSharedMemorySize, 98304);

    // acc = boundary_condition (self-loop messages)
    cudaMemcpyAsync(accPtr, boundary, (size_t)NN * EMBD * sizeof(float),
                    cudaMemcpyDeviceToDevice, 0);

    // prep: split W_msg into bf16 hi/lo images
    k0_prep_w<<<96, 256>>>(W_msg);

    // H1 = hidden @ W_msg[0:128] + b_msg   (HMMA)
    k1_node_hmma<<<(NN + 63) / 64, 256, K1_SMEM>>>(hidden, b_msg, (float*)h1Ptr);

    // edge messages (HMMA split-bf16, frag reuse) + scatter
    k2_edge_mma<<<(NE + 127) / 128, 512, K2_SMEM>>>(eattr, etime, eidx,
                                                    (const float*)h1Ptr, (float*)accPtr);

    // node update: GEMM + LN + relu + threefry dropout
    k3_update<<<(NN + 63) / 64, 256, 98304>>>((const float*)accPtr, W_lin, b_lin,
                                              gamma, beta, out);
}

// round 6
// speedup vs baseline: 1.1623x; 1.0369x over previous
#include <cuda_runtime.h>
#include <cuda_bf16.h>
#include <cstdint>

#define NN  50000
#define EMBD 128
#define NE  500000

// scratch (allocation-free rule: __device__ globals)
__device__ __align__(16) float g_H1[NN * EMBD];
__device__ __align__(16) float g_acc[NN * EMBD];
// pre-split bf16 images (row-major [k][n])
__device__ __align__(16) uint4 g_W1img_hi[2048];  // 32KB, W_msg[0:128,:]
__device__ __align__(16) uint4 g_W1img_lo[2048];
__device__ __align__(16) uint4 g_Bimg_hi[1024];   // 16KB, W_msg[128:192,:]
__device__ __align__(16) uint4 g_Bimg_lo[1024];
__device__ __align__(16) uint4 g_WLimg_hi[2048];  // 32KB, W_lin
__device__ __align__(16) uint4 g_WLimg_lo[2048];

// ---------------------------------------------------------------------------
// threefry2x32, JAX partitionable mode. key=(0,42), counter=(0, flat),
// output = out0 ^ out1.
// ---------------------------------------------------------------------------
__device__ __forceinline__ unsigned tf_rotl(unsigned x, int r) {
    return __funnelshift_l(x, x, r);
}
__device__ __forceinline__ unsigned threefry_bits(unsigned flat) {
    unsigned x0 = 0u, x1 = flat;
    const unsigned ks0 = 0u, ks1 = 42u, ks2 = 0x1BD11BDAu ^ 0u ^ 42u;
    x0 += ks0; x1 += ks1;
#define TF_R(r) { x0 += x1; x1 = tf_rotl(x1, r); x1 ^= x0; }
    TF_R(13) TF_R(15) TF_R(26) TF_R(6)
    x0 += ks1; x1 += ks2 + 1u;
    TF_R(17) TF_R(29) TF_R(16) TF_R(24)
    x0 += ks2; x1 += ks0 + 2u;
    TF_R(13) TF_R(15) TF_R(26) TF_R(6)
    x0 += ks0; x1 += ks1 + 3u;
    TF_R(17) TF_R(29) TF_R(16) TF_R(24)
    x0 += ks1; x1 += ks2 + 4u;
    TF_R(13) TF_R(15) TF_R(26) TF_R(6)
    x0 += ks2; x1 += ks0 + 5u;
#undef TF_R
    return x0 ^ x1;
}

// ---------------------------------------------------------------------------
// baseline-PTX helpers (no 'a'-gated features)
// ---------------------------------------------------------------------------
__device__ __forceinline__ uint32_t smem_u32(const void* p) {
    uint32_t a;
    asm("{ .reg .u64 t; cvta.to.shared.u64 t, %1; cvt.u32.u64 %0, t; }"
        : "=r"(a) : "l"(p));
    return a;
}
__device__ __forceinline__ void ldsm_x4(uint32_t addr, uint32_t* r) {
    asm volatile("ldmatrix.sync.aligned.m8n8.x4.shared.b16 {%0,%1,%2,%3}, [%4];"
                 : "=r"(r[0]), "=r"(r[1]), "=r"(r[2]), "=r"(r[3]) : "r"(addr));
}
__device__ __forceinline__ void ldsm_x4_t(uint32_t addr, uint32_t& r0, uint32_t& r1,
                                          uint32_t& r2, uint32_t& r3) {
    asm volatile("ldmatrix.sync.aligned.m8n8.x4.trans.shared.b16 {%0,%1,%2,%3}, [%4];"
                 : "=r"(r0), "=r"(r1), "=r"(r2), "=r"(r3) : "r"(addr));
}
__device__ __forceinline__ void mma16816(float* c, const uint32_t* a,
                                         uint32_t b0, uint32_t b1) {
    asm volatile(
        "mma.sync.aligned.m16n8k16.row.col.f32.bf16.bf16.f32 "
        "{%0,%1,%2,%3}, {%4,%5,%6,%7}, {%8,%9}, {%0,%1,%2,%3};"
        : "+f"(c[0]), "+f"(c[1]), "+f"(c[2]), "+f"(c[3])
        : "r"(a[0]), "r"(a[1]), "r"(a[2]), "r"(a[3]), "r"(b0), "r"(b1));
}
__device__ __forceinline__ void red_add_v4(float* p, float a, float b,
                                           float c, float d) {
    asm volatile("red.global.add.v4.f32 [%0], {%1, %2, %3, %4};"
                 :: "l"(p), "f"(a), "f"(b), "f"(c), "f"(d) : "memory");
}
__device__ __forceinline__ unsigned pack_bf2(__nv_bfloat16 a, __nv_bfloat16 b) {
    unsigned ua = (unsigned)__bfloat16_as_ushort(a);
    unsigned ub = (unsigned)__bfloat16_as_ushort(b);
    return ua | (ub << 16);
}
__device__ __forceinline__ void split_store(char* dh, char* dl, const float* xs) {
    unsigned hw[8], lw[8];
#pragma unroll
    for (int j = 0; j < 8; ++j) {
        __nv_bfloat16 h0 = __float2bfloat16(xs[j * 2 + 0]);
        __nv_bfloat16 h1 = __float2bfloat16(xs[j * 2 + 1]);
        __nv_bfloat16 l0 = __float2bfloat16(xs[j * 2 + 0] - __bfloat162float(h0));
        __nv_bfloat16 l1 = __float2bfloat16(xs[j * 2 + 1] - __bfloat162float(h1));
        hw[j] = pack_bf2(h0, h1);
        lw[j] = pack_bf2(l0, l1);
    }
    *(uint4*)dh        = make_uint4(hw[0], hw[1], hw[2], hw[3]);
    *(uint4*)(dh + 16) = make_uint4(hw[4], hw[5], hw[6], hw[7]);
    *(uint4*)dl        = make_uint4(lw[0], lw[1], lw[2], lw[3]);
    *(uint4*)(dl + 16) = make_uint4(lw[4], lw[5], lw[6], lw[7]);
}

// ---------------------------------------------------------------------------
// k0: split W_msg (24576) and W_lin (16384) into hi/lo bf16 images
// ---------------------------------------------------------------------------
__global__ __launch_bounds__(256) void k0_prep_w(const float* __restrict__ W_msg,
                                                 const float* __restrict__ W_lin) {
    int idx = blockIdx.x * 256 + threadIdx.x;      // 0..40959
    float x;
    if (idx < 24576) x = W_msg[idx];
    else             x = W_lin[idx - 24576];
    __nv_bfloat16 h = __float2bfloat16(x);
    __nv_bfloat16 l = __float2bfloat16(x - __bfloat162float(h));
    if (idx < 16384) {
        ((__nv_bfloat16*)g_W1img_hi)[idx] = h;
        ((__nv_bfloat16*)g_W1img_lo)[idx] = l;
    } else if (idx < 24576) {
        ((__nv_bfloat16*)g_Bimg_hi)[idx - 16384] = h;
        ((__nv_bfloat16*)g_Bimg_lo)[idx - 16384] = l;
    } else {
        ((__nv_bfloat16*)g_WLimg_hi)[idx - 24576] = h;
        ((__nv_bfloat16*)g_WLimg_lo)[idx - 24576] = l;
    }
}

// ---------------------------------------------------------------------------
// shared 64x128 HMMA GEMM body macros (K=128). A from gmem rows, B images.
// CTA = 64 rows x 128 cols, 256 thr, 8 warps (2m x 4n), warp = 32r x 32c.
// ---------------------------------------------------------------------------
#define K1_APITCH 272
#define K1_BPITCH 272
#define K1_AHI 0
#define K1_ALO 17408
#define K1_BHI 34816
#define K1_BLO 69632
#define K1_SMEM 104448

// loads A rows [row0,row0+64) from src (stride 128 f32) + B images; runs the
// split-bf16 GEMM; leaves results in acc[2][4][4]. Declares m0,n0,lane.
#define HMMA_64x128_BODY(SRC, BIMG_HI, BIMG_LO)                                    \
    const int tid = threadIdx.x;                                                   \
    const int lane = tid & 31, w = tid >> 5;                                       \
    {                                                                              \
        const uint4* bh = BIMG_HI;                                                 \
        const uint4* bl = BIMG_LO;                                                 \
        _Pragma("unroll")                                                          \
        for (int t = 0; t < 8; ++t) {                                              \
            int idx = tid + t * 256;                                               \
            int row = idx >> 4, seg = idx & 15;                                    \
            *(uint4*)(smc + K1_BHI + row * K1_BPITCH + seg * 16) = bh[idx];        \
            *(uint4*)(smc + K1_BLO + row * K1_BPITCH + seg * 16) = bl[idx];        \
        }                                                                          \
    }                                                                              \
    {                                                                              \
        int r = tid >> 2, q = tid & 3;                                             \
        int gr = row0 + r;                                                         \
        float xs[32];                                                              \
        if (gr < NN) {                                                             \
            const float4* p = (const float4*)(SRC + (size_t)gr * 128 + q * 32);    \
            _Pragma("unroll")                                                      \
            for (int i = 0; i < 8; ++i) {                                          \
                float4 f = p[i];                                                   \
                xs[i*4+0]=f.x; xs[i*4+1]=f.y; xs[i*4+2]=f.z; xs[i*4+3]=f.w;        \
            }                                                                      \
        } else {                                                                   \
            _Pragma("unroll")                                                      \
            for (int i = 0; i < 32; ++i) xs[i] = 0.f;                              \
        }                                                                          \
        split_store(smc + K1_AHI + r * K1_APITCH + q * 64,                         \
                    smc + K1_ALO + r * K1_APITCH + q * 64, xs);                    \
        split_store(smc + K1_AHI + r * K1_APITCH + q * 64 + 32,                    \
                    smc + K1_ALO + r * K1_APITCH + q * 64 + 32, xs + 16);          \
    }                                                                              \
    __syncthreads();                                                               \
    const int m0 = (w >> 2) * 32;                                                  \
    const int n0 = (w & 3) * 32;                                                   \
    float acc[2][4][4];                                                            \
    _Pragma("unroll")                                                              \
    for (int a = 0; a < 2; ++a)                                                    \
        _Pragma("unroll")                                                          \
        for (int b = 0; b < 4; ++b)                                                \
            _Pragma("unroll")                                                      \
            for (int c = 0; c < 4; ++c) acc[a][b][c] = 0.f;                        \
    const uint32_t arow = (uint32_t)(lane & 15);                                   \
    const uint32_t acol = (uint32_t)((lane >> 4) * 16);                            \
    _Pragma("unroll")                                                              \
    for (int k = 0; k < 8; ++k) {                                                  \
        uint32_t a0[4], a1[4];                                                     \
        uint32_t ad = sb + K1_AHI + (uint32_t)(m0 + arow) * K1_APITCH + k * 32 + acol; \
        ldsm_x4(ad, a0);                                                           \
        ldsm_x4(ad + 16 * K1_APITCH, a1);                                          \
        _Pragma("unroll")                                                          \
        for (int p = 0; p < 2; ++p) {                                              \
            uint32_t bd = sb + K1_BHI + (uint32_t)(k * 16 + arow) * K1_BPITCH      \
                        + (uint32_t)(n0 + p * 16) * 2 + acol;                      \
            uint32_t h0,h1,h2,h3, l0,l1,l2,l3;                                     \
            ldsm_x4_t(bd, h0, h1, h2, h3);                                         \
            ldsm_x4_t(bd + (K1_BLO - K1_BHI), l0, l1, l2, l3);                     \
            mma16816(acc[0][p*2],   a0, h0, h1);                                   \
            mma16816(acc[0][p*2+1], a0, h2, h3);                                   \
            mma16816(acc[1][p*2],   a1, h0, h1);                                   \
            mma16816(acc[1][p*2+1], a1, h2, h3);                                   \
            mma16816(acc[0][p*2],   a0, l0, l1);                                   \
            mma16816(acc[0][p*2+1], a0, l2, l3);                                   \
            mma16816(acc[1][p*2],   a1, l0, l1);                                   \
            mma16816(acc[1][p*2+1], a1, l2, l3);                                   \
        }                                                                          \
    }                                                                              \
    _Pragma("unroll")                                                              \
    for (int k = 0; k < 8; ++k) {                                                  \
        uint32_t a0[4], a1[4];                                                     \
        uint32_t ad = sb + K1_ALO + (uint32_t)(m0 + arow) * K1_APITCH + k * 32 + acol; \
        ldsm_x4(ad, a0);                                                           \
        ldsm_x4(ad + 16 * K1_APITCH, a1);                                          \
        _Pragma("unroll")                                                          \
        for (int p = 0; p < 2; ++p) {                                              \
            uint32_t bd = sb + K1_BHI + (uint32_t)(k * 16 + arow) * K1_BPITCH      \
                        + (uint32_t)(n0 + p * 16) * 2 + acol;                      \
            uint32_t h0,h1,h2,h3;                                                  \
            ldsm_x4_t(bd, h0, h1, h2, h3);                                         \
            mma16816(acc[0][p*2],   a0, h0, h1);                                   \
            mma16816(acc[0][p*2+1], a0, h2, h3);                                   \
            mma16816(acc[1][p*2],   a1, h0, h1);                                   \
            mma16816(acc[1][p*2+1], a1, h2, h3);                                   \
        }                                                                          \
    }

// ---------------------------------------------------------------------------
// k1: H1 = hidden @ W1 + b_msg
// ---------------------------------------------------------------------------
__global__ __launch_bounds__(256) void k1_node_hmma(
    const float* __restrict__ A, const float* __restrict__ bias,
    float* __restrict__ out)
{
    extern __shared__ char smc[];
    const uint32_t sb = smem_u32(smc);
    const int row0 = blockIdx.x * 64;
    HMMA_64x128_BODY(A, g_W1img_hi, g_W1img_lo)

#pragma unroll
    for (int mt = 0; mt < 2; ++mt) {
#pragma unroll
        for (int half = 0; half < 2; ++half) {
            int r = row0 + m0 + mt * 16 + (lane >> 2) + half * 8;
            if (r < NN) {
                float* o = out + (size_t)r * 128;
#pragma unroll
                for (int nt = 0; nt < 4; ++nt) {
                    int j = n0 + nt * 8 + (lane & 3) * 2;
                    float2 b2 = *(const float2*)(bias + j);
                    float2 v;
                    v.x = acc[mt][nt][half * 2 + 0] + b2.x;
                    v.y = acc[mt][nt][half * 2 + 1] + b2.y;
                    *(float2*)(o + j) = v;
                }
            }
        }
    }
}

// ---------------------------------------------------------------------------
// k2: split-bf16 edge GEMM (HMMA) + gather/relu + red.v4 scatter.
// CTA = 128 edges x 128 cols, 512 thr, 16 warps (4m x 4n), warp = 32e x 32c.
// ---------------------------------------------------------------------------
#define K2_APITCH 144
#define K2_BPITCH 272
#define K2_AHI 0
#define K2_ALO 18432
#define K2_BHI 36864
#define K2_BLO 54272
#define K2_IDX 71680
#define K2_SMEM 72704

__global__ __launch_bounds__(512) void k2_edge_mma(
    const float* __restrict__ eattr, const float* __restrict__ etime,
    const int* __restrict__ eidx, const float* __restrict__ H1,
    float* __restrict__ accum)
{
    extern __shared__ char smc[];
    const uint32_t sb = smem_u32(smc);
    const int tid = threadIdx.x;
    const int lane = tid & 31, w = tid >> 5;
    const int e0 = blockIdx.x * 128;
    int* s_src = (int*)(smc + K2_IDX);
    int* s_dst = s_src + 128;

    if (tid < 256) {
        int r = tid & 127;
        int e = e0 + r;
        int v = (e < NE) ? eidx[(tid < 128 ? 0 : NE) + e] : 0;
        if (tid < 128) s_src[r] = v; else s_dst[r] = v;
    }
    {
        const uint4* bh = g_Bimg_hi;
        const uint4* bl = g_Bimg_lo;
#pragma unroll
        for (int t = 0; t < 2; ++t) {
            int idx = tid + t * 512;
            int row = idx >> 4, seg = idx & 15;
            *(uint4*)(smc + K2_BHI + row * K2_BPITCH + seg * 16) = bh[idx];
            *(uint4*)(smc + K2_BLO + row * K2_BPITCH + seg * 16) = bl[idx];
        }
    }
    {
        int ed = tid >> 2, q = tid & 3;
        int e = e0 + ed;
        float xs[16];
        if (e < NE) {
            const float4* p = (q < 2) ? ((const float4*)(eattr + (size_t)e * 32) + q * 4)
                                      : ((const float4*)(etime + (size_t)e * 32) + (q - 2) * 4);
            float4 f0 = p[0], f1 = p[1], f2 = p[2], f3 = p[3];
            xs[0]=f0.x; xs[1]=f0.y; xs[2]=f0.z; xs[3]=f0.w;
            xs[4]=f1.x; xs[5]=f1.y; xs[6]=f1.z; xs[7]=f1.w;
            xs[8]=f2.x; xs[9]=f2.y; xs[10]=f2.z; xs[11]=f2.w;
            xs[12]=f3.x; xs[13]=f3.y; xs[14]=f3.z; xs[15]=f3.w;
        } else {
#pragma unroll
            for (int i = 0; i < 16; ++i) xs[i] = 0.f;
        }
        split_store(smc + K2_AHI + ed * K2_APITCH + q * 32,
                    smc + K2_ALO + ed * K2_APITCH + q * 32, xs);
    }
    __syncthreads();

    const int m0 = (w >> 2) * 32;
    const int n0 = (w & 3) * 32;

    float acc[2][4][4];
#pragma unroll
    for (int a = 0; a < 2; ++a)
#pragma unroll
        for (int b = 0; b < 4; ++b)
#pragma unroll
            for (int c = 0; c < 4; ++c) acc[a][b][c] = 0.f;

    const uint32_t arow = (uint32_t)(lane & 15);
    const uint32_t acol = (uint32_t)((lane >> 4) * 16);

#pragma unroll
    for (int k = 0; k < 4; ++k) {
        uint32_t a0[4], a1[4];
        uint32_t ad = sb + K2_AHI + (uint32_t)(m0 + arow) * K2_APITCH + k * 32 + acol;
        ldsm_x4(ad, a0);
        ldsm_x4(ad + 16 * K2_APITCH, a1);
#pragma unroll
        for (int p = 0; p < 2; ++p) {
            uint32_t bd = sb + K2_BHI + (uint32_t)(k * 16 + arow) * K2_BPITCH
                        + (uint32_t)(n0 + p * 16) * 2 + acol;
            uint32_t h0,h1,h2,h3, l0,l1,l2,l3;
            ldsm_x4_t(bd, h0, h1, h2, h3);
            ldsm_x4_t(bd + (K2_BLO - K2_BHI), l0, l1, l2, l3);
            mma16816(acc[0][p*2],   a0, h0, h1);
            mma16816(acc[0][p*2+1], a0, h2, h3);
            mma16816(acc[1][p*2],   a1, h0, h1);
            mma16816(acc[1][p*2+1], a1, h2, h3);
            mma16816(acc[0][p*2],   a0, l0, l1);
            mma16816(acc[0][p*2+1], a0, l2, l3);
            mma16816(acc[1][p*2],   a1, l0, l1);
            mma16816(acc[1][p*2+1], a1, l2, l3);
        }
    }
#pragma unroll
    for (int k = 0; k < 4; ++k) {
        uint32_t a0[4], a1[4];
        uint32_t ad = sb + K2_ALO + (uint32_t)(m0 + arow) * K2_APITCH + k * 32 + acol;
        ldsm_x4(ad, a0);
        ldsm_x4(ad + 16 * K2_APITCH, a1);
#pragma unroll
        for (int p = 0; p < 2; ++p) {
            uint32_t bd = sb + K2_BHI + (uint32_t)(k * 16 + arow) * K2_BPITCH
                        + (uint32_t)(n0 + p * 16) * 2 + acol;
            uint32_t h0,h1,h2,h3;
            ldsm_x4_t(bd, h0, h1, h2, h3);
            mma16816(acc[0][p*2],   a0, h0, h1);
            mma16816(acc[0][p*2+1], a0, h2, h3);
            mma16816(acc[1][p*2],   a1, h0, h1);
            mma16816(acc[1][p*2+1], a1, h2, h3);
        }
    }

    // epilogue: gather H1[src], relu; merge lane pairs -> red.v4 into acc[dst]
#pragma unroll
    for (int mt = 0; mt < 2; ++mt) {
#pragma unroll
        for (int half = 0; half < 2; ++half) {
            int r = m0 + mt * 16 + (lane >> 2) + half * 8;
            bool valid = (e0 + r) < NE;
            const float* hp = H1 + (size_t)s_src[r] * 128;
            float* ap = accum + (size_t)s_dst[r] * 128;
#pragma unroll
            for (int nt = 0; nt < 4; ++nt) {
                int j = n0 + nt * 8 + (lane & 3) * 2;
                float2 h = *(const float2*)(hp + j);
                float v0 = fmaxf(acc[mt][nt][half * 2 + 0] + h.x, 0.f);
                float v1 = fmaxf(acc[mt][nt][half * 2 + 1] + h.y, 0.f);
                float w0 = __shfl_down_sync(0xffffffffu, v0, 1);
                float w1 = __shfl_down_sync(0xffffffffu, v1, 1);
                if (valid && ((lane & 1) == 0)) {
                    red_add_v4(ap + j, v0, v1, w0, w1);
                }
            }
        }
    }
}

// ---------------------------------------------------------------------------
// k3: out = dropout(relu(LN(acc @ W_lin + b_lin)))  — HMMA GEMM, smem-staged
// LN/threefry epilogue (warp per row).
// ---------------------------------------------------------------------------
#define K3_OPITCH 132   // floats per staged output row

__global__ __launch_bounds__(256) void k3_hmma(
    const float* __restrict__ A, const float* __restrict__ bias,
    const float* __restrict__ gamma, const float* __restrict__ beta,
    float* __restrict__ out)
{
    extern __shared__ char smc[];
    const uint32_t sb = smem_u32(smc);
    const int row0 = blockIdx.x * 64;
    HMMA_64x128_BODY(A, g_WLimg_hi, g_WLimg_lo)

    // stage raw GEMM result in smem (reuse A-tile region; all ldsm done)
    __syncthreads();
    float* so = (float*)smc;    // 64 rows x K3_OPITCH
#pragma unroll
    for (int mt = 0; mt < 2; ++mt) {
#pragma unroll
        for (int half = 0; half < 2; ++half) {
            int rl = m0 + mt * 16 + (lane >> 2) + half * 8;
#pragma unroll
            for (int nt = 0; nt < 4; ++nt) {
                int j = n0 + nt * 8 + (lane & 3) * 2;
                float2 v;
                v.x = acc[mt][nt][half * 2 + 0];
                v.y = acc[mt][nt][half * 2 + 1];
                *(float2*)(so + rl * K3_OPITCH + j) = v;
            }
        }
    }
    __syncthreads();

    // LN + relu + threefry dropout: warp w handles rows w*8 .. w*8+7
    const int tx = lane;
    float bb[4] = { bias[tx], bias[tx + 32], bias[tx + 64], bias[tx + 96] };
    float gm[4] = { gamma[tx], gamma[tx + 32], gamma[tx + 64], gamma[tx + 96] };
    float bt[4] = { beta[tx],  beta[tx + 32],  beta[tx + 64],  beta[tx + 96] };

#pragma unroll
    for (int i = 0; i < 8; ++i) {
        int rl = w * 8 + i;
        int r = row0 + rl;
        float v[4];
#pragma unroll
        for (int c = 0; c < 4; ++c) v[c] = so[rl * K3_OPITCH + tx + 32 * c] + bb[c];
        float s = v[0] + v[1] + v[2] + v[3];
#pragma unroll
        for (int off = 16; off; off >>= 1) s += __shfl_xor_sync(0xffffffffu, s, off);
        float mean = s * (1.0f / 128.0f);
        float d[4];
        float ss = 0.f;
#pragma unroll
        for (int c = 0; c < 4; ++c) { d[c] = v[c] - mean; ss += d[c] * d[c]; }
#pragma unroll
        for (int off = 16; off; off >>= 1) ss += __shfl_xor_sync(0xffffffffu, ss, off);
        float rstd = rsqrtf(ss * (1.0f / 128.0f) + 1e-5f);

        if (r < NN) {
            float* o = out + (size_t)r * 128;
#pragma unroll
            for (int c = 0; c < 4; ++c) {
                int j = tx + 32 * c;
                float y = d[c] * rstd * gm[c] + bt[c];
                y = fmaxf(y, 0.f);
                unsigned bits = threefry_bits((unsigned)(r * 128 + j));
                float u = __uint_as_float((bits >> 9) | 0x3F800000u) - 1.0f;
                o[j] = (u < 0.9f) ? (y / 0.9f) : 0.f;
            }
        }
    }
}

// ---------------------------------------------------------------------------
extern "C" void kernel_launch(void* const* d_in, const int* in_sizes, int n_in,
                              void* d_out, int out_size) {
    (void)in_sizes; (void)n_in; (void)out_size;
    const float* hidden   = (const float*)d_in[0];
    const int*   eidx     = (const int*)d_in[1];
    const float* eattr    = (const float*)d_in[2];
    const float* etime    = (const float*)d_in[3];
    const float* boundary = (const float*)d_in[4];
    const float* W_msg    = (const float*)d_in[5];
    const float* b_msg    = (const float*)d_in[6];
    const float* W_lin    = (const float*)d_in[7];
    const float* b_lin    = (const float*)d_in[8];
    const float* gamma    = (const float*)d_in[9];
    const float* beta     = (const float*)d_in[10];
    float* out = (float*)d_out;

    void* h1Ptr = nullptr;
    void* accPtr = nullptr;
    cudaGetSymbolAddress(&h1Ptr, g_H1);
    cudaGetSymbolAddress(&accPtr, g_acc);

    cudaFuncSetAttribute(k1_node_hmma, cudaFuncAttributeMaxDynamicSharedMemorySize, K1_SMEM);
    cudaFuncSetAttribute(k2_edge_mma,  cudaFuncAttributeMaxDynamicSharedMemorySize, K2_SMEM);
    cudaFuncSetAttribute(k3_hmma,      cudaFuncAttributeMaxDynamicSharedMemorySize, K1_SMEM);

    // acc = boundary_condition (self-loop messages)
    cudaMemcpyAsync(accPtr, boundary, (size_t)NN * EMBD * sizeof(float),
                    cudaMemcpyDeviceToDevice, 0);

    // prep: split W_msg + W_lin into bf16 hi/lo images
    k0_prep_w<<<160, 256>>>(W_msg, W_lin);

    // H1 = hidden @ W_msg[0:128] + b_msg   (HMMA)
    k1_node_hmma<<<(NN + 63) / 64, 256, K1_SMEM>>>(hidden, b_msg, (float*)h1Ptr);

    // edge messages (HMMA split-bf16) + red.v4 scatter
    k2_edge_mma<<<(NE + 127) / 128, 512, K2_SMEM>>>(eattr, etime, eidx,
                                                    (const float*)h1Ptr, (float*)accPtr);

    // node update: HMMA GEMM + LN + relu + threefry dropout
    k3_hmma<<<(NN + 63) / 64, 256, K1_SMEM>>>((const float*)accPtr, b_lin,
                                              gamma, beta, out);
}